// round 1
// baseline (speedup 1.0000x reference)
#include <cuda_runtime.h>
#include <math_constants.h>

// Problem shape assumptions (from reference setup_inputs): V=1024 fixed;
// B, L, T derived from in_sizes. Scratch sized for B<=64, T<=1024, S<=222.
#define VOCAB      1024
#define MAXB       64
#define MAXT       1024
#define SP         224           // padded extended-state stride (>= S = 2L+1)
#define P1_THREADS 128
#define P2_THREADS 256

#define LOG2E_F 1.4426950408889634f
#define LN2_F   0.6931471805599453f
#define NEG_LN  (-1e30f)
#define NEG2_C  (-1.4426950408889634e30f)   // NEG_LN * LOG2E

static __device__ __forceinline__ float fex2(float x) {
    float y; asm("ex2.approx.f32 %0, %1;" : "=f"(y) : "f"(x)); return y;
}
static __device__ __forceinline__ float flg2(float x) {
    float y; asm("lg2.approx.f32 %0, %1;" : "=f"(y) : "f"(x)); return y;
}

// Scratch: compact per-(b,t) extended-label log2-probs, and per-batch loss.
__device__ float g_lp[(size_t)MAXB * MAXT * SP];
__device__ float g_loss[MAXB];

// ---------------------------------------------------------------------------
// Pass 1: per-row log-softmax normalizer (base-2) + gather of the S extended
// labels into compact scratch. One CTA of 128 threads per (b,t) row.
// ---------------------------------------------------------------------------
__global__ void __launch_bounds__(P1_THREADS)
lse_gather_kernel(const float* __restrict__ pred,
                  const int*   __restrict__ gt,
                  int T, int V, int L, int S)
{
    extern __shared__ float sm[];         // V floats row cache + 32 reduce
    float* srow = sm;
    float* sred = sm + V;

    const int row = blockIdx.x;           // b*T + t
    const int b   = row / T;
    const int tid = threadIdx.x;
    const int lane = tid & 31, wid = tid >> 5;

    const float* __restrict__ p = pred + (size_t)row * V;

    // Vectorized load into SMEM, tracking local max.
    float lmax = -CUDART_INF_F;
    for (int i = tid * 4; i < V; i += P1_THREADS * 4) {
        float4 v = *reinterpret_cast<const float4*>(p + i);
        *reinterpret_cast<float4*>(srow + i) = v;
        lmax = fmaxf(lmax, fmaxf(fmaxf(v.x, v.y), fmaxf(v.z, v.w)));
    }
    #pragma unroll
    for (int o = 16; o; o >>= 1)
        lmax = fmaxf(lmax, __shfl_xor_sync(0xffffffffu, lmax, o));
    if (lane == 0) sred[wid] = lmax;
    __syncthreads();
    float bm = fmaxf(fmaxf(sred[0], sred[1]), fmaxf(sred[2], sred[3]));
    __syncthreads();

    // Sum of exp2((x - max) * log2e)
    float lsum = 0.f;
    for (int i = tid; i < V; i += P1_THREADS)
        lsum += fex2((srow[i] - bm) * LOG2E_F);
    #pragma unroll
    for (int o = 16; o; o >>= 1)
        lsum += __shfl_xor_sync(0xffffffffu, lsum, o);
    if (lane == 0) sred[wid] = lsum;
    __syncthreads();
    float bs   = sred[0] + sred[1] + sred[2] + sred[3];
    float lse2 = bm * LOG2E_F + flg2(bs);   // log2(sum exp) of the row

    // Gather extended labels: lp2[s] = pred[b,t,ext[s]]*log2e - lse2
    float* __restrict__ out = g_lp + (size_t)row * SP;
    const int* __restrict__ gtb = gt + (size_t)b * L;
    for (int s = tid; s < S; s += P1_THREADS) {
        int lab = 0;
        if (s & 1) {
            int idx = (s >> 1); if (idx > L - 1) idx = L - 1;
            lab = gtb[idx];
        }
        out[s] = srow[lab] * LOG2E_F - lse2;
    }
}

// ---------------------------------------------------------------------------
// Pass 2: CTC forward recursion. One CTA per batch, one thread per extended
// state, SMEM double buffer, 1 barrier/step, depth-4 lp prefetch pipeline.
// Everything in log2 units.
// ---------------------------------------------------------------------------
__global__ void __launch_bounds__(P2_THREADS)
ctc_forward_kernel(const int* __restrict__ plen,
                   const int* __restrict__ gt,
                   const int* __restrict__ gtl,
                   int T, int L, int S)
{
    __shared__ float buf0[SP + 2];
    __shared__ float buf1[SP + 2];

    const int b   = blockIdx.x;
    const int tid = threadIdx.x;
    const int ilen = plen[b];
    const int tl   = gtl[b];
    const float* __restrict__ lp = g_lp + (size_t)b * T * SP;
    const int* __restrict__ gtb = gt + (size_t)b * L;

    const bool isS = (tid < S);

    // Static skip predicate per state: s>=2 && ext[s]!=blank && ext[s]!=ext[s-2]
    bool skip = false;
    if (isS && tid >= 2 && (tid & 1)) {
        int i0 = (tid >> 1);     if (i0 > L - 1) i0 = L - 1;
        int i2 = (tid >> 1) - 1; if (i2 > L - 1) i2 = L - 1;
        int lab = gtb[i0], labm2 = gtb[i2];
        skip = (lab != 0) && (lab != labm2);
    }

    // Init alpha(t=0)
    if (tid < 2) { buf0[tid] = NEG2_C; buf1[tid] = NEG2_C; }
    if (isS) {
        float a = NEG2_C;
        if (tid == 0) a = lp[0];
        else if (tid == 1 && tl > 0) a = lp[1];
        buf0[2 + tid] = a;
    }
    __syncthreads();

    float final2 = NEG2_C;   // only tid 0's copy is meaningful
    if (tid == 0 && ilen == 1) {
        int s1 = 2 * tl, s2 = (2 * tl - 1 > 0) ? 2 * tl - 1 : 0;
        float e1 = buf0[2 + s1], e2 = buf0[2 + s2];
        float mm = fmaxf(e1, e2);
        final2 = mm + flg2(fex2(e1 - mm) + fex2(e2 - mm));
    }

    // Prefetch pipeline (depth 4) of lp rows t=1..4
    float pl0 = 0.f, pl1 = 0.f, pl2 = 0.f, pl3 = 0.f;
    if (isS) {
        if (1 < T) pl0 = lp[(size_t)1 * SP + tid];
        if (2 < T) pl1 = lp[(size_t)2 * SP + tid];
        if (3 < T) pl2 = lp[(size_t)3 * SP + tid];
        if (4 < T) pl3 = lp[(size_t)4 * SP + tid];
    }

    float* A = buf0;
    float* B = buf1;

#define CTC_STEP(TCUR, LPREG)                                               \
    do {                                                                     \
        int t_ = (TCUR);                                                     \
        if (t_ < T) {                                                        \
            float lpc = LPREG;                                               \
            int tn_ = t_ + 4;                                                \
            if (isS && tn_ < T) LPREG = lp[(size_t)tn_ * SP + tid];          \
            if (isS) {                                                       \
                float a0 = A[2 + tid];                                       \
                float a1 = A[1 + tid];                                       \
                float a2 = skip ? A[tid] : NEG2_C;                           \
                float m  = fmaxf(a0, fmaxf(a1, a2));                         \
                float sum = fex2(a0 - m) + fex2(a1 - m) + fex2(a2 - m);      \
                float r = m + flg2(sum) + lpc;                               \
                B[2 + tid] = (t_ < ilen) ? r : a0;                           \
            }                                                                \
            __syncthreads();                                                 \
            { float* tmp__ = A; A = B; B = tmp__; }                          \
            if (tid == 0 && t_ == ilen - 1) {                                \
                int s1_ = 2 * tl;                                            \
                int s2_ = (2 * tl - 1 > 0) ? 2 * tl - 1 : 0;                 \
                float e1 = A[2 + s1_], e2 = A[2 + s2_];                      \
                float mm = fmaxf(e1, e2);                                    \
                final2 = mm + flg2(fex2(e1 - mm) + fex2(e2 - mm));           \
            }                                                                \
        }                                                                    \
    } while (0)

    for (int tb = 1; tb < T; tb += 4) {
        CTC_STEP(tb + 0, pl0);
        CTC_STEP(tb + 1, pl1);
        CTC_STEP(tb + 2, pl2);
        CTC_STEP(tb + 3, pl3);
    }
#undef CTC_STEP

    if (tid == 0) {
        float fin  = final2 * LN2_F;           // back to natural log
        float loss = -fin;
        if (fin <= NEG_LN * 0.5f) loss = 0.f;  // zero_infinity
        g_loss[b] = loss / (float)tl;
    }
}

// ---------------------------------------------------------------------------
// Pass 3: deterministic batch-mean reduction (single warp).
// ---------------------------------------------------------------------------
__global__ void reduce_loss_kernel(float* __restrict__ out, int B)
{
    float v = 0.f;
    for (int i = threadIdx.x; i < B; i += 32) v += g_loss[i];
    #pragma unroll
    for (int o = 16; o; o >>= 1) v += __shfl_xor_sync(0xffffffffu, v, o);
    if (threadIdx.x == 0) out[0] = v / (float)B;
}

// ---------------------------------------------------------------------------
extern "C" void kernel_launch(void* const* d_in, const int* in_sizes, int n_in,
                              void* d_out, int out_size)
{
    const float* pred = (const float*)d_in[0];
    const int*   plen = (const int*)d_in[1];
    const int*   gt   = (const int*)d_in[2];
    const int*   gtl  = (const int*)d_in[3];

    const int B = in_sizes[1];
    const int L = in_sizes[2] / B;
    const int V = VOCAB;
    const int T = in_sizes[0] / (B * V);
    const int S = 2 * L + 1;

    size_t smem = (size_t)(V + 32) * sizeof(float);
    lse_gather_kernel<<<B * T, P1_THREADS, smem>>>(pred, gt, T, V, L, S);
    ctc_forward_kernel<<<B, P2_THREADS>>>(plen, gt, gtl, T, L, S);
    reduce_loss_kernel<<<1, 32>>>((float*)d_out, B);
}

// round 3
// speedup vs baseline: 3.1533x; 3.1533x over previous
#include <cuda_runtime.h>
#include <math_constants.h>

// Shapes: V=1024 fixed; B,L,T from in_sizes. Scratch for B<=64, T<=1024, S<=256.
#define VOCAB      1024
#define MAXB       64
#define MAXT       1024
#define SP         256           // padded extended-state stride (>= S = 2L+1), 8 per lane
#define P1_THREADS 128
#define FULLMASK   0xffffffffu

#define LOG2E_F 1.4426950408889634f
#define LN2_F   0.6931471805599453f

static __device__ __forceinline__ float fex2(float x) {
    float y; asm("ex2.approx.f32 %0, %1;" : "=f"(y) : "f"(x)); return y;
}

// Scratch: per-(b,t) extended-label PROBABILITIES (softmax, gathered), padded to 256.
__device__ float g_p[(size_t)MAXB * MAXT * SP];
__device__ float g_loss[MAXB];

// ---------------------------------------------------------------------------
// Pass 1: per-row softmax + gather of the S extended-label probs into compact
// scratch (prob domain). One CTA of 128 threads per (b,t) row.
// ---------------------------------------------------------------------------
__global__ void __launch_bounds__(P1_THREADS)
softmax_gather_kernel(const float* __restrict__ pred,
                      const int*   __restrict__ gt,
                      int T, int L, int S)
{
    __shared__ float srow[VOCAB];
    __shared__ float sred[32];

    const int row = blockIdx.x;           // b*T + t
    const int b   = row / T;
    const int tid = threadIdx.x;
    const int lane = tid & 31, wid = tid >> 5;

    const float* __restrict__ p = pred + (size_t)row * VOCAB;

    float lmax = -CUDART_INF_F;
    {
        float4 v0 = *reinterpret_cast<const float4*>(p + tid * 4);
        float4 v1 = *reinterpret_cast<const float4*>(p + tid * 4 + 512);
        *reinterpret_cast<float4*>(srow + tid * 4)       = v0;
        *reinterpret_cast<float4*>(srow + tid * 4 + 512) = v1;
        lmax = fmaxf(fmaxf(fmaxf(v0.x, v0.y), fmaxf(v0.z, v0.w)),
                     fmaxf(fmaxf(v1.x, v1.y), fmaxf(v1.z, v1.w)));
    }
    #pragma unroll
    for (int o = 16; o; o >>= 1)
        lmax = fmaxf(lmax, __shfl_xor_sync(FULLMASK, lmax, o));
    if (lane == 0) sred[wid] = lmax;
    __syncthreads();
    float bm = fmaxf(fmaxf(sred[0], sred[1]), fmaxf(sred[2], sred[3]));
    __syncthreads();

    float lsum = 0.f;
    #pragma unroll
    for (int k = 0; k < VOCAB / P1_THREADS; k++)
        lsum += fex2((srow[tid + k * P1_THREADS] - bm) * LOG2E_F);
    #pragma unroll
    for (int o = 16; o; o >>= 1)
        lsum += __shfl_xor_sync(FULLMASK, lsum, o);
    if (lane == 0) sred[wid] = lsum;
    __syncthreads();
    float bs     = sred[0] + sred[1] + sred[2] + sred[3];
    float inv_bs = __frcp_rn(bs);

    float* __restrict__ out = g_p + (size_t)row * SP;
    const int* __restrict__ gtb = gt + (size_t)b * L;
    #pragma unroll
    for (int k = 0; k < SP / P1_THREADS; k++) {
        int s = tid + k * P1_THREADS;
        float v = 0.f;
        if (s < S) {
            int lab = 0;
            if (s & 1) {
                int idx = (s >> 1); if (idx > L - 1) idx = L - 1;
                lab = gtb[idx];
            }
            v = fex2((srow[lab] - bm) * LOG2E_F) * inv_bs;
        }
        out[s] = v;
    }
}

// ---------------------------------------------------------------------------
// Pass 2: CTC forward recursion, prob domain with PER-LANE block floating
// point. One warp per batch; lane l owns states [8l, 8l+8) with its own int
// exponent El (true alpha = stored * 2^El). Cross-lane terms scaled by the
// exact factor f = 2^(El_left - El), recomputed at each renorm (every 4
// steps). Zero lanes adopt the left neighbor's exponent so the wavefront
// always crosses lane boundaries with f exact.
// ---------------------------------------------------------------------------
__global__ void __launch_bounds__(32)
ctc_forward_kernel(const int* __restrict__ plen,
                   const int* __restrict__ gt,
                   const int* __restrict__ gtl,
                   int T, int L, int S)
{
    const int b    = blockIdx.x;
    const int lane = threadIdx.x;
    const int ilen = min(plen[b], T);
    const int tl   = gtl[b];
    const float* __restrict__ Pb = g_p + (size_t)b * T * SP + lane * 8;
    const int* __restrict__ gtb = gt + (size_t)b * L;

    // Static skip masks (1.0f where the 2-step transition is allowed)
    float m[8];
    #pragma unroll
    for (int j = 0; j < 8; j++) {
        int s = lane * 8 + j;
        float mm = 0.f;
        if (s >= 2 && (s & 1) && s < S) {
            int lab = gtb[s >> 1], lm2 = gtb[(s >> 1) - 1];
            mm = (lab != 0 && lab != lm2) ? 1.f : 0.f;
        }
        m[j] = mm;
    }

    // alpha(t=0)
    float a[8];
    #pragma unroll
    for (int j = 0; j < 8; j++) a[j] = 0.f;
    if (lane == 0) {
        float4 q0 = *reinterpret_cast<const float4*>(Pb);
        a[0] = q0.x;
        a[1] = (tl > 0) ? q0.y : 0.f;
    }

    int   El = 0;                          // per-lane exponent
    float f  = (lane == 0) ? 0.f : 1.f;    // 2^(El_left - El); lane 0 has no left
    const int nsteps = ilen - 1;           // recursion runs t = 1 .. ilen-1

#define CTC_STEP(Q0, Q1)                                                    \
    do {                                                                     \
        float u7 = __shfl_up_sync(FULLMASK, a[7], 1) * f;                    \
        float u6 = __shfl_up_sync(FULLMASK, a[6], 1) * f;                    \
        float n0 = fmaf(m[0], u6,   a[0] + u7)   * (Q0).x;                   \
        float n1 = fmaf(m[1], u7,   a[1] + a[0]) * (Q0).y;                   \
        float n2 = fmaf(m[2], a[0], a[2] + a[1]) * (Q0).z;                   \
        float n3 = fmaf(m[3], a[1], a[3] + a[2]) * (Q0).w;                   \
        float n4 = fmaf(m[4], a[2], a[4] + a[3]) * (Q1).x;                   \
        float n5 = fmaf(m[5], a[3], a[5] + a[4]) * (Q1).y;                   \
        float n6 = fmaf(m[6], a[4], a[6] + a[5]) * (Q1).z;                   \
        float n7 = fmaf(m[7], a[5], a[7] + a[6]) * (Q1).w;                   \
        a[0]=n0; a[1]=n1; a[2]=n2; a[3]=n3; a[4]=n4; a[5]=n5; a[6]=n6; a[7]=n7; \
    } while (0)

    // Per-lane renorm + exponent bookkeeping (exact power-of-2 arithmetic).
#define CTC_RENORM()                                                        \
    do {                                                                     \
        float mx = fmaxf(fmaxf(fmaxf(a[0], a[1]), fmaxf(a[2], a[3])),       \
                         fmaxf(fmaxf(a[4], a[5]), fmaxf(a[6], a[7])));       \
        bool nz = (mx > 0.f);                                                \
        int  e  = nz ? ((__float_as_int(mx) >> 23) - 127) : 0;               \
        int  Elp = El + e;                                                   \
        int  Eleft = __shfl_up_sync(FULLMASK, Elp, 1);                       \
        if (!nz && lane > 0) Elp = Eleft;      /* adopt neighbor's scale */  \
        if (nz) {                                                            \
            float sc = __int_as_float((127 - e) << 23);                      \
            _Pragma("unroll")                                                \
            for (int j = 0; j < 8; j++) a[j] *= sc;                          \
        }                                                                    \
        El = Elp;                                                            \
        int El2 = __shfl_up_sync(FULLMASK, El, 1);                           \
        int dE  = El2 - El;                                                  \
        if (lane == 0 || dE < -126) f = 0.f;                                 \
        else f = __int_as_float((min(dE, 126) + 127) << 23);                 \
    } while (0)

    // Prefetch pipeline, depth 8 (one p-row = 2 float4 per lane per step)
    float4 pf0[8], pf1[8];
    #pragma unroll
    for (int k = 0; k < 8; k++) {
        int r = min(1 + k, T - 1);
        pf0[k] = *reinterpret_cast<const float4*>(Pb + (size_t)r * SP);
        pf1[k] = *reinterpret_cast<const float4*>(Pb + (size_t)r * SP + 4);
    }

    int t = 1;
    for (; t + 7 <= nsteps; t += 8) {
        #pragma unroll
        for (int k = 0; k < 8; k++) {
            float4 q0 = pf0[k], q1 = pf1[k];
            int r = min(t + k + 8, T - 1);
            pf0[k] = *reinterpret_cast<const float4*>(Pb + (size_t)r * SP);
            pf1[k] = *reinterpret_cast<const float4*>(Pb + (size_t)r * SP + 4);
            CTC_STEP(q0, q1);
            if (k == 3 || k == 7) CTC_RENORM();
        }
    }
    for (; t <= nsteps; t++) {
        float4 q0 = *reinterpret_cast<const float4*>(Pb + (size_t)t * SP);
        float4 q1 = *reinterpret_cast<const float4*>(Pb + (size_t)t * SP + 4);
        CTC_STEP(q0, q1);
    }
#undef CTC_STEP
#undef CTC_RENORM

    // end_ll over alpha[2*tl] (lane1/slot1) and alpha[max(2*tl-1,0)] (lane2/slot2)
    int s1 = 2 * tl;
    int s2 = (2 * tl - 1 > 0) ? (2 * tl - 1) : 0;
    int lane1 = s1 >> 3, slot1 = s1 & 7;
    int lane2 = s2 >> 3, slot2 = s2 & 7;
    float v1 = a[0], v2 = a[0];
    #pragma unroll
    for (int j = 1; j < 8; j++) { v1 = (slot1 == j) ? a[j] : v1;
                                  v2 = (slot2 == j) ? a[j] : v2; }
    int   E1 = __shfl_sync(FULLMASK, El, lane1);
    int   E2 = __shfl_sync(FULLMASK, El, lane2);
    v1 = __shfl_sync(FULLMASK, v1, lane1);
    v2 = __shfl_sync(FULLMASK, v2, lane2);

    if (lane == 0) {
        // log2 of each term with exact exponent; accurate logaddexp of the two
        float l1 = (v1 > 0.f) ? (log2f(v1) + (float)E1) : -3.0e38f;
        float l2 = (v2 > 0.f) ? (log2f(v2) + (float)E2) : -3.0e38f;
        float mm = fmaxf(l1, l2);
        float loss;
        if (mm < -2.0e38f) {
            loss = 0.f;                    // zero_infinity: p == 0
        } else {
            float tot2 = mm + log2f(exp2f(l1 - mm) + exp2f(l2 - mm));
            loss = -tot2 * LN2_F;
        }
        g_loss[b] = loss / (float)tl;
    }
}

// ---------------------------------------------------------------------------
// Pass 3: deterministic batch-mean reduction (single warp).
// ---------------------------------------------------------------------------
__global__ void reduce_loss_kernel(float* __restrict__ out, int B)
{
    float v = 0.f;
    for (int i = threadIdx.x; i < B; i += 32) v += g_loss[i];
    #pragma unroll
    for (int o = 16; o; o >>= 1) v += __shfl_xor_sync(FULLMASK, v, o);
    if (threadIdx.x == 0) out[0] = v / (float)B;
}

// ---------------------------------------------------------------------------
extern "C" void kernel_launch(void* const* d_in, const int* in_sizes, int n_in,
                              void* d_out, int out_size)
{
    const float* pred = (const float*)d_in[0];
    const int*   plen = (const int*)d_in[1];
    const int*   gt   = (const int*)d_in[2];
    const int*   gtl  = (const int*)d_in[3];

    const int B = in_sizes[1];
    const int L = in_sizes[2] / B;
    const int T = in_sizes[0] / (B * VOCAB);
    const int S = 2 * L + 1;

    softmax_gather_kernel<<<B * T, P1_THREADS>>>(pred, gt, T, L, S);
    ctc_forward_kernel<<<B, 32>>>(plen, gt, gtl, T, L, S);
    reduce_loss_kernel<<<1, 32>>>((float*)d_out, B);
}